// round 1
// baseline (speedup 1.0000x reference)
#include <cuda_runtime.h>
#include <math.h>

// Problem dims
constexpr int BB = 64;    // batch
constexpr int TT = 256;   // time steps
constexpr int II = 256;   // input dim
constexpr int HH = 1024;  // hidden
constexpr int CC = 60;    // classes
constexpr int GG = 4096;  // 4*H

// Scratch (allocation-free: __device__ globals)
__device__ float g_xproj[TT * BB * GG];   // [t][b][g], 268 MB
__device__ float g_h[2][BB * HH];         // ping-pong hidden state
__device__ float g_c[BB * HH];            // cell state (block-private per h-col slice)

// ---------------------------------------------------------------------------
// Zero-init h (both buffers) and c. Deterministic every call.
// ---------------------------------------------------------------------------
__global__ void zero_kernel() {
    int i = blockIdx.x * blockDim.x + threadIdx.x;
    if (i < 2 * BB * HH) ((float*)g_h)[i] = 0.f;
    if (i < BB * HH) g_c[i] = 0.f;
}

// ---------------------------------------------------------------------------
// x_proj[t][b][g] = sum_i inputs[b][t][i] * W_ih[g][i] + b_ih[g] + b_hh[g]
// Tile: 64 rows (all b for one t) x 64 cols, K=256 in chunks of 32.
// 256 threads, 4x4 microtile, double-buffered SMEM.
// grid: (GG/64, TT)
// ---------------------------------------------------------------------------
__global__ __launch_bounds__(256) void xproj_kernel(
    const float* __restrict__ inp, const float* __restrict__ Wih,
    const float* __restrict__ bih, const float* __restrict__ bhh) {
    __shared__ float sa[2][32][68];   // [k][b]
    __shared__ float sb[2][32][68];   // [k][n_local]
    int tid = threadIdx.x;
    int tr = tid >> 4, tc = tid & 15;     // 16x16 thread grid
    int t = blockIdx.y;
    int n0 = blockIdx.x * 64;
    int lk = tid & 31, lr = tid >> 5;     // loader: k-in-chunk, row-group 0..7

    float acc[4][4];
#pragma unroll
    for (int r = 0; r < 4; r++)
#pragma unroll
        for (int c = 0; c < 4; c++) acc[r][c] = 0.f;

    // prologue: chunk 0
#pragma unroll
    for (int i = 0; i < 8; i++) {
        int m = 8 * i + lr;                        // batch row
        sa[0][lk][m] = inp[(m * TT + t) * II + lk];
        int n = n0 + 8 * i + lr;
        sb[0][lk][8 * i + lr] = Wih[n * II + lk];
    }
    __syncthreads();

#pragma unroll 2
    for (int ch = 0; ch < 8; ch++) {
        int cb = ch & 1;
        float ra[8], rb[8];
        if (ch < 7) {
            int k0 = (ch + 1) * 32;
#pragma unroll
            for (int i = 0; i < 8; i++) {
                int m = 8 * i + lr;
                ra[i] = inp[(m * TT + t) * II + k0 + lk];
                int n = n0 + 8 * i + lr;
                rb[i] = Wih[n * II + k0 + lk];
            }
        }
#pragma unroll
        for (int kk = 0; kk < 32; kk++) {
            float4 av = *(const float4*)&sa[cb][kk][4 * tr];
            float4 bv = *(const float4*)&sb[cb][kk][4 * tc];
            acc[0][0] += av.x * bv.x; acc[0][1] += av.x * bv.y; acc[0][2] += av.x * bv.z; acc[0][3] += av.x * bv.w;
            acc[1][0] += av.y * bv.x; acc[1][1] += av.y * bv.y; acc[1][2] += av.y * bv.z; acc[1][3] += av.y * bv.w;
            acc[2][0] += av.z * bv.x; acc[2][1] += av.z * bv.y; acc[2][2] += av.z * bv.z; acc[2][3] += av.z * bv.w;
            acc[3][0] += av.w * bv.x; acc[3][1] += av.w * bv.y; acc[3][2] += av.w * bv.z; acc[3][3] += av.w * bv.w;
        }
        if (ch < 7) {
            int nb = cb ^ 1;
#pragma unroll
            for (int i = 0; i < 8; i++) { sa[nb][lk][8 * i + lr] = ra[i]; sb[nb][lk][8 * i + lr] = rb[i]; }
            __syncthreads();
        }
    }

    // epilogue: add biases, store
#pragma unroll
    for (int r = 0; r < 4; r++) {
        int b = 4 * tr + r;
        int g = n0 + 4 * tc;
        float4 bi = *(const float4*)&bih[g];
        float4 bh = *(const float4*)&bhh[g];
        float4 o;
        o.x = acc[r][0] + bi.x + bh.x;
        o.y = acc[r][1] + bi.y + bh.y;
        o.z = acc[r][2] + bi.z + bh.z;
        o.w = acc[r][3] + bi.w + bh.w;
        *(float4*)&g_xproj[((size_t)t * BB + b) * GG + g] = o;
    }
}

// ---------------------------------------------------------------------------
// One LSTM step: gates[b, g] = x_proj[t][b][g] + sum_k h[b][k] * W_hh[g][k],
// then fused pointwise update of (h, c) for this block's 8 h-columns x 4 gates.
// grid: 128 blocks (each owns h-cols [8*bx, 8*bx+8) across all 4 gates).
// 256 threads, 4 rows x 2 cols microtile, K=1024 in chunks of 32, dbl-buffered.
// ---------------------------------------------------------------------------
__global__ __launch_bounds__(256) void step_kernel(const float* __restrict__ Whh, int t) {
    __shared__ float sh[2][32][68];   // h chunk [k][b]
    __shared__ float sw[2][32][34];   // W chunk [k][col]
    int tid = threadIdx.x;
    int tr = tid >> 4, tc = tid & 15;   // rows 4*tr.., cols 2*tc..
    int hc0 = blockIdx.x * 8;
    int lk = tid & 31, lr = tid >> 5;

    const float* hin = g_h[t & 1];
    float* hout = g_h[(t + 1) & 1];
    const float* xg = g_xproj + (size_t)t * BB * GG;

    float acc[4][2] = {{0, 0}, {0, 0}, {0, 0}, {0, 0}};

    // prologue: chunk 0
#pragma unroll
    for (int i = 0; i < 8; i++) sh[0][lk][8 * i + lr] = hin[(8 * i + lr) * HH + lk];
#pragma unroll
    for (int i = 0; i < 4; i++) {
        int g = i * HH + hc0 + lr;                 // gate i, col lr
        sw[0][lk][8 * i + lr] = Whh[g * HH + lk];
    }
    __syncthreads();

#pragma unroll 2
    for (int ch = 0; ch < 32; ch++) {
        int cb = ch & 1;
        float rh[8], rw[4];
        if (ch < 31) {
            int k0 = (ch + 1) * 32;
#pragma unroll
            for (int i = 0; i < 8; i++) rh[i] = hin[(8 * i + lr) * HH + k0 + lk];
#pragma unroll
            for (int i = 0; i < 4; i++) {
                int g = i * HH + hc0 + lr;
                rw[i] = Whh[g * HH + k0 + lk];
            }
        }
#pragma unroll
        for (int kk = 0; kk < 32; kk++) {
            float4 hv = *(const float4*)&sh[cb][kk][4 * tr];
            float2 wv = *(const float2*)&sw[cb][kk][2 * tc];
            acc[0][0] += hv.x * wv.x; acc[0][1] += hv.x * wv.y;
            acc[1][0] += hv.y * wv.x; acc[1][1] += hv.y * wv.y;
            acc[2][0] += hv.z * wv.x; acc[2][1] += hv.z * wv.y;
            acc[3][0] += hv.w * wv.x; acc[3][1] += hv.w * wv.y;
        }
        if (ch < 31) {
            int nb = cb ^ 1;
#pragma unroll
            for (int i = 0; i < 8; i++) sh[nb][lk][8 * i + lr] = rh[i];
#pragma unroll
            for (int i = 0; i < 4; i++) sw[nb][lk][8 * i + lr] = rw[i];
            __syncthreads();
        }
    }

    // exchange gate values via SMEM (reuse sh[0]: last read was chunk 30, synced).
    float* shg = &sh[0][0][0];  // shg[cl*68 + b], cl = q*8 + j
#pragma unroll
    for (int r = 0; r < 4; r++) {
#pragma unroll
        for (int cc = 0; cc < 2; cc++) {
            int b = 4 * tr + r;
            int cl = 2 * tc + cc;
            int g = ((cl >> 3) << 10) + hc0 + (cl & 7);
            shg[cl * 68 + b] = acc[r][cc] + xg[(size_t)b * GG + g];
        }
    }
    __syncthreads();

    // pointwise LSTM update: 64 b x 8 j = 512 states, 2 per thread
#pragma unroll
    for (int p = tid; p < 512; p += 256) {
        int b = p & 63, j = p >> 6;
        float iv = shg[j * 68 + b];
        float fv = shg[(8 + j) * 68 + b];
        float gv = shg[(16 + j) * 68 + b];
        float ov = shg[(24 + j) * 68 + b];
        float si = 1.f / (1.f + expf(-iv));
        float sf = 1.f / (1.f + expf(-fv));
        float tg = tanhf(gv);
        float so = 1.f / (1.f + expf(-ov));
        int idx = b * HH + hc0 + j;
        float cn = sf * g_c[idx] + si * tg;
        g_c[idx] = cn;
        hout[idx] = so * tanhf(cn);
    }
}

// ---------------------------------------------------------------------------
// logits = h_last @ fc_w^T + fc_b; out = log_softmax(logits)
// one block per batch row, 64 threads (c < 60 active)
// ---------------------------------------------------------------------------
__global__ void fc_kernel(const float* __restrict__ fcw, const float* __restrict__ fcb,
                          float* __restrict__ out) {
    int b = blockIdx.x;
    int c = threadIdx.x;
    __shared__ float sl[64];
    __shared__ float s_mx, s_lse;
    float v = -1e30f;
    if (c < CC) {
        const float4* hr = (const float4*)&g_h[0][b * HH];   // T=256 even -> final h in buf 0
        const float4* wr = (const float4*)&fcw[c * HH];
        float a0 = 0, a1 = 0, a2 = 0, a3 = 0;
        for (int k = 0; k < HH / 4; k++) {
            float4 hv = hr[k], wv = wr[k];
            a0 += hv.x * wv.x; a1 += hv.y * wv.y; a2 += hv.z * wv.z; a3 += hv.w * wv.w;
        }
        v = a0 + a1 + a2 + a3 + fcb[c];
    }
    sl[c] = v;
    __syncthreads();
    if (c == 0) {
        float mx = -1e30f;
        for (int k = 0; k < CC; k++) mx = fmaxf(mx, sl[k]);
        float s = 0.f;
        for (int k = 0; k < CC; k++) s += expf(sl[k] - mx);
        s_mx = mx;
        s_lse = logf(s);
    }
    __syncthreads();
    if (c < CC) out[b * CC + c] = v - s_mx - s_lse;
}

// ---------------------------------------------------------------------------
extern "C" void kernel_launch(void* const* d_in, const int* in_sizes, int n_in,
                              void* d_out, int out_size) {
    const float* inp = (const float*)d_in[0];   // [B,T,I]
    const float* Wih = (const float*)d_in[1];   // [4H,I]
    const float* Whh = (const float*)d_in[2];   // [4H,H]
    const float* bih = (const float*)d_in[3];   // [4H]
    const float* bhh = (const float*)d_in[4];   // [4H]
    const float* fcw = (const float*)d_in[5];   // [C,H]
    const float* fcb = (const float*)d_in[6];   // [C]
    float* out = (float*)d_out;                 // [B,C]

    zero_kernel<<<512, 256>>>();

    dim3 g1(GG / 64, TT);
    xproj_kernel<<<g1, 256>>>(inp, Wih, bih, bhh);

    for (int t = 0; t < TT; t++) step_kernel<<<128, 256>>>(Whh, t);

    fc_kernel<<<BB, 64>>>(fcw, fcb, out);
}

// round 3
// speedup vs baseline: 2.4178x; 2.4178x over previous
#include <cuda_runtime.h>
#include <cuda_bf16.h>
#include <math.h>
#include <cstdint>

// Problem dims
constexpr int BB = 64;    // batch
constexpr int TT = 256;   // time steps
constexpr int II = 256;   // input dim
constexpr int HH = 1024;  // hidden
constexpr int CC = 60;    // classes
constexpr int GG = 4096;  // 4*H
constexpr int NCTA = 128; // persistent CTAs; each owns 8 h-cols x 4 gates = 32 gate cols

// Dynamic SMEM layout (lstm_kernel)
constexpr int A_HI = 0;        // 2 bufs x 8KB  (64 rows x 64 bf16, SW128)
constexpr int A_LO = 16384;    // 2 bufs x 8KB
constexpr int WF_HI = 32768;   // 64KB fragment-direct W hi
constexpr int WF_LO = 98304;   // 64KB fragment-direct W lo
constexpr int SMEM_DYN = 163840;

// Scratch (__device__ globals: allocation-free)
__device__ float g_xproj[(size_t)TT * BB * GG];   // [t][b][g]
__device__ __nv_bfloat16 g_hhi[2][BB * HH];       // h hi, ping-pong
__device__ __nv_bfloat16 g_hlo[2][BB * HH];       // h lo, ping-pong
__device__ unsigned g_bar;                        // grid barrier counter

// ---------------------------------------------------------------------------
// helpers
// ---------------------------------------------------------------------------
__device__ __forceinline__ uint32_t smem_u32(const void* p) {
    uint32_t a;
    asm("{ .reg .u64 t; cvta.to.shared.u64 t, %1; cvt.u32.u64 %0, t; }" : "=r"(a) : "l"(p));
    return a;
}
__device__ __forceinline__ void ldm_x4(uint32_t* r, uint32_t addr) {
    asm volatile("ldmatrix.sync.aligned.m8n8.x4.shared.b16 {%0,%1,%2,%3}, [%4];"
                 : "=r"(r[0]), "=r"(r[1]), "=r"(r[2]), "=r"(r[3]) : "r"(addr));
}
__device__ __forceinline__ void mma_bf16(float* d, const uint32_t* a, uint32_t b0, uint32_t b1) {
    asm volatile(
        "mma.sync.aligned.m16n8k16.row.col.f32.bf16.bf16.f32 "
        "{%0,%1,%2,%3}, {%4,%5,%6,%7}, {%8,%9}, {%0,%1,%2,%3};"
        : "+f"(d[0]), "+f"(d[1]), "+f"(d[2]), "+f"(d[3])
        : "r"(a[0]), "r"(a[1]), "r"(a[2]), "r"(a[3]), "r"(b0), "r"(b1));
}

// ---------------------------------------------------------------------------
// Zero-init h buffers (both) + barrier counter. Deterministic each call.
// ---------------------------------------------------------------------------
__global__ void zero_kernel() {
    int i = blockIdx.x * blockDim.x + threadIdx.x;
    if (i < BB * HH) {            // uint words span 2 bf16 -> 2*BB*HH bf16 per array
        ((unsigned*)g_hhi)[i] = 0u;
        ((unsigned*)g_hlo)[i] = 0u;
    }
    if (i == 0) g_bar = 0u;
}

// ---------------------------------------------------------------------------
// x_proj[t][b][g] = inputs[b][t][:] . W_ih[g][:] + b_ih[g] + b_hh[g]
// (fp32 GEMM, proven in round 1)
// ---------------------------------------------------------------------------
__global__ __launch_bounds__(256) void xproj_kernel(
    const float* __restrict__ inp, const float* __restrict__ Wih,
    const float* __restrict__ bih, const float* __restrict__ bhh) {
    __shared__ float sa[2][32][68];
    __shared__ float sb[2][32][68];
    int tid = threadIdx.x;
    int tr = tid >> 4, tc = tid & 15;
    int t = blockIdx.y;
    int n0 = blockIdx.x * 64;
    int lk = tid & 31, lr = tid >> 5;

    float acc[4][4];
#pragma unroll
    for (int r = 0; r < 4; r++)
#pragma unroll
        for (int c = 0; c < 4; c++) acc[r][c] = 0.f;

#pragma unroll
    for (int i = 0; i < 8; i++) {
        int m = 8 * i + lr;
        sa[0][lk][m] = inp[(m * TT + t) * II + lk];
        int n = n0 + 8 * i + lr;
        sb[0][lk][8 * i + lr] = Wih[n * II + lk];
    }
    __syncthreads();

#pragma unroll 2
    for (int ch = 0; ch < 8; ch++) {
        int cb = ch & 1;
        float ra[8], rb[8];
        if (ch < 7) {
            int k0 = (ch + 1) * 32;
#pragma unroll
            for (int i = 0; i < 8; i++) {
                int m = 8 * i + lr;
                ra[i] = inp[(m * TT + t) * II + k0 + lk];
                int n = n0 + 8 * i + lr;
                rb[i] = Wih[n * II + k0 + lk];
            }
        }
#pragma unroll
        for (int kk = 0; kk < 32; kk++) {
            float4 av = *(const float4*)&sa[cb][kk][4 * tr];
            float4 bv = *(const float4*)&sb[cb][kk][4 * tc];
            acc[0][0] += av.x * bv.x; acc[0][1] += av.x * bv.y; acc[0][2] += av.x * bv.z; acc[0][3] += av.x * bv.w;
            acc[1][0] += av.y * bv.x; acc[1][1] += av.y * bv.y; acc[1][2] += av.y * bv.z; acc[1][3] += av.y * bv.w;
            acc[2][0] += av.z * bv.x; acc[2][1] += av.z * bv.y; acc[2][2] += av.z * bv.z; acc[2][3] += av.z * bv.w;
            acc[3][0] += av.w * bv.x; acc[3][1] += av.w * bv.y; acc[3][2] += av.w * bv.z; acc[3][3] += av.w * bv.w;
        }
        if (ch < 7) {
            int nb = cb ^ 1;
#pragma unroll
            for (int i = 0; i < 8; i++) { sa[nb][lk][8 * i + lr] = ra[i]; sb[nb][lk][8 * i + lr] = rb[i]; }
            __syncthreads();
        }
    }

#pragma unroll
    for (int r = 0; r < 4; r++) {
        int b = 4 * tr + r;
        int g = n0 + 4 * tc;
        float4 bi = *(const float4*)&bih[g];
        float4 bh = *(const float4*)&bhh[g];
        float4 o;
        o.x = acc[r][0] + bi.x + bh.x;
        o.y = acc[r][1] + bi.y + bh.y;
        o.z = acc[r][2] + bi.z + bh.z;
        o.w = acc[r][3] + bi.w + bh.w;
        *(float4*)&g_xproj[((size_t)t * BB + b) * GG + g] = o;
    }
}

// ---------------------------------------------------------------------------
// Persistent LSTM recurrence: 128 CTAs x 256 thr. mma.sync bf16 3-term split.
// Warp w: m-tile mt=w&3 (16 batch rows), n-half nh=w>>2 (16 gate cols, 2 n8 tiles).
// W pre-permuted to fragment-direct SMEM (one LDS.128 = both n-tiles' {b0,b1}).
// h streamed per step as 16 double-buffered 64x64 bf16 chunks (hi & lo).
// ---------------------------------------------------------------------------
__global__ __launch_bounds__(256, 1) void lstm_kernel(const float* __restrict__ Whh) {
    extern __shared__ char sm[];
    const int tid = threadIdx.x;
    const int lane = tid & 31;
    const int w = tid >> 5;
    const int mt = w & 3, nh = w >> 2;
    const int hc0 = blockIdx.x * 8;
    const uint32_t smb = smem_u32(sm);

    // ---- one-time: W fragment fill (hi/lo split, fragment-direct layout) ----
    // element index idx = ((nh*64 + kstep)*32 + lane)*4 + r
    for (int idx = tid; idx < 16384; idx += 256) {
        int r = idx & 3, ln = (idx >> 2) & 31, ks = (idx >> 7) & 63, nhh = idx >> 13;
        int nt = r >> 1;
        int kk = (r & 1) * 8 + (ln & 3) * 2;
        int nl = nhh * 16 + nt * 8 + (ln >> 2);           // CTA-local gate col 0..31
        int k = ks * 16 + kk;
        int gr = (nl >> 3) * 1024 + hc0 + (nl & 7);        // global gate row
        float w0 = Whh[gr * 1024 + k];
        float w1 = Whh[gr * 1024 + k + 1];
        __nv_bfloat16 h0 = __float2bfloat16(w0), h1 = __float2bfloat16(w1);
        __nv_bfloat16 l0 = __float2bfloat16(w0 - __bfloat162float(h0));
        __nv_bfloat16 l1 = __float2bfloat16(w1 - __bfloat162float(h1));
        uint32_t hp = (uint32_t)*(uint16_t*)&h0 | ((uint32_t)*(uint16_t*)&h1 << 16);
        uint32_t lp = (uint32_t)*(uint16_t*)&l0 | ((uint32_t)*(uint16_t*)&l1 << 16);
        ((uint32_t*)(sm + WF_HI))[idx] = hp;
        ((uint32_t*)(sm + WF_LO))[idx] = lp;
    }
    __syncthreads();

    // per-thread A-chunk staging constants (2 x 16B segments per thread)
    const int row0 = tid >> 3, s0 = tid & 7;
    const int row1 = (tid + 256) >> 3, s1 = tid & 7;
    int o0 = row0 * 128 + s0 * 16; o0 ^= (o0 >> 3) & 0x70;
    int o1 = row1 * 128 + s1 * 16; o1 ^= (o1 >> 3) & 0x70;

    // A ldmatrix per-lane constants
    const int arow = mt * 16 + (lane & 15);
    const int acol = (lane >> 4) * 16;   // byte offset of k-half

    float creg[8] = {0, 0, 0, 0, 0, 0, 0, 0};

    for (int t = 0; t < TT; t++) {
        const uint4* ghi = (const uint4*)g_hhi[t & 1];
        const uint4* glo = (const uint4*)g_hlo[t & 1];
        const float* xg = g_xproj + (size_t)t * BB * GG;

        // prefetch this CTA's xproj slice for the epilogue (warps 0,1)
        float xp[32];
        if (tid < 64) {
            const float* xb = xg + (size_t)tid * GG + hc0;
#pragma unroll
            for (int q = 0; q < 4; q++) {
                *(float4*)&xp[q * 8] = *(const float4*)(xb + q * HH);
                *(float4*)&xp[q * 8 + 4] = *(const float4*)(xb + q * HH + 4);
            }
        }

        float acc[2][4];
#pragma unroll
        for (int z = 0; z < 2; z++)
#pragma unroll
            for (int r = 0; r < 4; r++) acc[z][r] = 0.f;

        // prologue: chunk 0 -> buf 0
        {
            uint4 vh0 = __ldcg(ghi + row0 * 128 + s0);
            uint4 vh1 = __ldcg(ghi + row1 * 128 + s1);
            uint4 vl0 = __ldcg(glo + row0 * 128 + s0);
            uint4 vl1 = __ldcg(glo + row1 * 128 + s1);
            *(uint4*)(sm + A_HI + o0) = vh0; *(uint4*)(sm + A_HI + o1) = vh1;
            *(uint4*)(sm + A_LO + o0) = vl0; *(uint4*)(sm + A_LO + o1) = vl1;
        }
        __syncthreads();

        for (int ch = 0; ch < 16; ch++) {
            const int buf = ch & 1;
            uint4 vh0, vh1, vl0, vl1;
            if (ch < 15) {
                int g0 = row0 * 128 + (ch + 1) * 8 + s0;
                int g1 = row1 * 128 + (ch + 1) * 8 + s1;
                vh0 = __ldcg(ghi + g0); vh1 = __ldcg(ghi + g1);
                vl0 = __ldcg(glo + g0); vl1 = __ldcg(glo + g1);
            }
            const uint32_t abh = smb + A_HI + buf * 8192;
            const uint32_t abl = smb + A_LO + buf * 8192;
            const uint32_t* wfh = (const uint32_t*)(sm + WF_HI) + (nh * 64 + ch * 4) * 128 + lane * 4;
            const uint32_t* wfl = (const uint32_t*)(sm + WF_LO) + (nh * 64 + ch * 4) * 128 + lane * 4;
#pragma unroll
            for (int kl = 0; kl < 4; kl++) {
                int off = arow * 128 + kl * 32 + acol;
                int sw = off ^ ((off >> 3) & 0x70);
                uint32_t ah[4], al[4];
                ldm_x4(ah, abh + sw);
                ldm_x4(al, abl + sw);
                uint4 bh = *(const uint4*)(wfh + kl * 128);
                uint4 bl = *(const uint4*)(wfl + kl * 128);
                mma_bf16(acc[0], ah, bh.x, bh.y);
                mma_bf16(acc[1], ah, bh.z, bh.w);
                mma_bf16(acc[0], al, bh.x, bh.y);
                mma_bf16(acc[1], al, bh.z, bh.w);
                mma_bf16(acc[0], ah, bl.x, bl.y);
                mma_bf16(acc[1], ah, bl.z, bl.w);
            }
            if (ch < 15) {
                char* dh = sm + A_HI + (buf ^ 1) * 8192;
                char* dl = sm + A_LO + (buf ^ 1) * 8192;
                *(uint4*)(dh + o0) = vh0; *(uint4*)(dh + o1) = vh1;
                *(uint4*)(dl + o0) = vl0; *(uint4*)(dl + o1) = vl1;
            }
            __syncthreads();
        }

        // epilogue: exchange D fragments via SMEM [32 cols][stride 72]
        float* sg = (float*)sm;
        {
            int grp = lane >> 2, tg = lane & 3;
#pragma unroll
            for (int nt = 0; nt < 2; nt++) {
                int col = nh * 16 + nt * 8 + tg * 2;
                int row = mt * 16 + grp;
                sg[col * 72 + row] = acc[nt][0];
                sg[(col + 1) * 72 + row] = acc[nt][1];
                sg[col * 72 + row + 8] = acc[nt][2];
                sg[(col + 1) * 72 + row + 8] = acc[nt][3];
            }
        }
        __syncthreads();

        if (tid < 64) {
            int b = tid;
            __align__(16) __nv_bfloat16 ho[16];
#pragma unroll
            for (int j = 0; j < 8; j++) {
                float iv = sg[j * 72 + b] + xp[j];
                float fv = sg[(8 + j) * 72 + b] + xp[8 + j];
                float gv = sg[(16 + j) * 72 + b] + xp[16 + j];
                float ov = sg[(24 + j) * 72 + b] + xp[24 + j];
                float si = 1.f / (1.f + expf(-iv));
                float sf = 1.f / (1.f + expf(-fv));
                float tg2 = tanhf(gv);
                float so = 1.f / (1.f + expf(-ov));
                float cn = sf * creg[j] + si * tg2;
                creg[j] = cn;
                float hn = so * tanhf(cn);
                __nv_bfloat16 hh = __float2bfloat16(hn);
                ho[j] = hh;
                ho[8 + j] = __float2bfloat16(hn - __bfloat162float(hh));
            }
            *(uint4*)(g_hhi[(t + 1) & 1] + b * HH + hc0) = *(uint4*)&ho[0];
            *(uint4*)(g_hlo[(t + 1) & 1] + b * HH + hc0) = *(uint4*)&ho[8];
        }
        __threadfence();
        __syncthreads();
        if (tid == 0) {
            atomicAdd(&g_bar, 1u);
            unsigned target = (unsigned)NCTA * (t + 1), v;
            do {
                asm volatile("ld.acquire.gpu.global.u32 %0, [%1];" : "=r"(v) : "l"(&g_bar));
            } while (v < target);
        }
        __syncthreads();
    }
}

// ---------------------------------------------------------------------------
// logits = h_last @ fc_w^T + fc_b; out = log_softmax  (h = hi + lo, buffer 0)
// ---------------------------------------------------------------------------
__global__ void fc_kernel(const float* __restrict__ fcw, const float* __restrict__ fcb,
                          float* __restrict__ out) {
    int b = blockIdx.x;
    int c = threadIdx.x;
    __shared__ float sl[64];
    __shared__ float s_mx, s_lse;
    float v = -1e30f;
    if (c < CC) {
        const __nv_bfloat16* hh = g_hhi[0] + b * HH;   // T=256 even -> final h in buf 0
        const __nv_bfloat16* hl = g_hlo[0] + b * HH;
        const float* wr = &fcw[c * HH];
        float a0 = 0.f;
        for (int k = 0; k < HH; k++) {
            float hv = __bfloat162float(hh[k]) + __bfloat162float(hl[k]);
            a0 += hv * wr[k];
        }
        v = a0 + fcb[c];
    }
    sl[c] = v;
    __syncthreads();
    if (c == 0) {
        float mx = -1e30f;
        for (int k = 0; k < CC; k++) mx = fmaxf(mx, sl[k]);
        float s = 0.f;
        for (int k = 0; k < CC; k++) s += expf(sl[k] - mx);
        s_mx = mx;
        s_lse = logf(s);
    }
    __syncthreads();
    if (c < CC) out[b * CC + c] = v - s_mx - s_lse;
}

// ---------------------------------------------------------------------------
extern "C" void kernel_launch(void* const* d_in, const int* in_sizes, int n_in,
                              void* d_out, int out_size) {
    const float* inp = (const float*)d_in[0];   // [B,T,I]
    const float* Wih = (const float*)d_in[1];   // [4H,I]
    const float* Whh = (const float*)d_in[2];   // [4H,H]
    const float* bih = (const float*)d_in[3];   // [4H]
    const float* bhh = (const float*)d_in[4];   // [4H]
    const float* fcw = (const float*)d_in[5];   // [C,H]
    const float* fcb = (const float*)d_in[6];   // [C]
    float* out = (float*)d_out;                 // [B,C]

    cudaFuncSetAttribute(lstm_kernel, cudaFuncAttributeMaxDynamicSharedMemorySize, SMEM_DYN);

    zero_kernel<<<512, 256>>>();

    dim3 g1(GG / 64, TT);
    xproj_kernel<<<g1, 256>>>(inp, Wih, bih, bhh);

    lstm_kernel<<<NCTA, 256, SMEM_DYN>>>(Whh);

    fc_kernel<<<BB, 64>>>(fcw, fcb, out);
}

// round 4
// speedup vs baseline: 2.5295x; 1.0462x over previous
#include <cuda_runtime.h>
#include <cuda_bf16.h>
#include <math.h>
#include <cstdint>

// Problem dims
constexpr int BB = 64;    // batch
constexpr int TT = 256;   // time steps
constexpr int II = 256;   // input dim
constexpr int HH = 1024;  // hidden
constexpr int CC = 60;    // classes
constexpr int GG = 4096;  // 4*H
constexpr int NCTA = 128; // persistent CTAs; each owns 8 h-cols x 4 gates = 32 gate cols

// Dynamic SMEM layout (lstm_kernel)
constexpr int A_HI = 0;        // 2 bufs x 8KB  (64 rows x 64 bf16, SW128)
constexpr int A_LO = 16384;    // 2 bufs x 8KB
constexpr int WF_HI = 32768;   // 64KB fragment-direct W hi
constexpr int WF_LO = 98304;   // 64KB fragment-direct W lo
constexpr int SMEM_DYN = 163840;

// Dynamic SMEM layout (xproj_mma kernel)
constexpr int XA_HI = 0;       // 2 bufs x 16KB (128 rows x 64 bf16, SW128)
constexpr int XA_LO = 32768;   // 2 bufs x 16KB
constexpr int XW_HI = 65536;   // 32KB fragment-direct W_ih hi (64 cols x 256 k)
constexpr int XW_LO = 98304;   // 32KB
constexpr int SMEM_X = 131072;

// Scratch (__device__ globals: allocation-free)
__device__ float g_xproj[(size_t)TT * BB * GG];   // [t][b][g]
__device__ __nv_bfloat16 g_hhi[2][BB * HH];       // h hi, ping-pong
__device__ __nv_bfloat16 g_hlo[2][BB * HH];       // h lo, ping-pong
__device__ __nv_bfloat16 g_xhi[BB * TT * II];     // inputs hi  [(b*T+t)][i]
__device__ __nv_bfloat16 g_xlo[BB * TT * II];
__device__ __nv_bfloat16 g_wihhi[GG * II];        // W_ih hi [g][i]
__device__ __nv_bfloat16 g_wihlo[GG * II];
__device__ unsigned g_bar;                        // grid barrier counter

// ---------------------------------------------------------------------------
// helpers
// ---------------------------------------------------------------------------
__device__ __forceinline__ uint32_t smem_u32(const void* p) {
    uint32_t a;
    asm("{ .reg .u64 t; cvta.to.shared.u64 t, %1; cvt.u32.u64 %0, t; }" : "=r"(a) : "l"(p));
    return a;
}
__device__ __forceinline__ void ldm_x4(uint32_t* r, uint32_t addr) {
    asm volatile("ldmatrix.sync.aligned.m8n8.x4.shared.b16 {%0,%1,%2,%3}, [%4];"
                 : "=r"(r[0]), "=r"(r[1]), "=r"(r[2]), "=r"(r[3]) : "r"(addr));
}
__device__ __forceinline__ void mma_bf16(float* d, const uint32_t* a, uint32_t b0, uint32_t b1) {
    asm volatile(
        "mma.sync.aligned.m16n8k16.row.col.f32.bf16.bf16.f32 "
        "{%0,%1,%2,%3}, {%4,%5,%6,%7}, {%8,%9}, {%0,%1,%2,%3};"
        : "+f"(d[0]), "+f"(d[1]), "+f"(d[2]), "+f"(d[3])
        : "r"(a[0]), "r"(a[1]), "r"(a[2]), "r"(a[3]), "r"(b0), "r"(b1));
}
__device__ __forceinline__ uint32_t pack2(__nv_bfloat16 a, __nv_bfloat16 b) {
    return (uint32_t)*(uint16_t*)&a | ((uint32_t)*(uint16_t*)&b << 16);
}
__device__ __forceinline__ float2 unpack2(uint32_t v) {
    __nv_bfloat16 a, b;
    uint16_t x = (uint16_t)v, y = (uint16_t)(v >> 16);
    a = *(__nv_bfloat16*)&x; b = *(__nv_bfloat16*)&y;
    return make_float2(__bfloat162float(a), __bfloat162float(b));
}

// ---------------------------------------------------------------------------
// Zero-init h buffers + barrier counter.
// ---------------------------------------------------------------------------
__global__ void zero_kernel() {
    int i = blockIdx.x * blockDim.x + threadIdx.x;
    if (i < BB * HH) {
        ((unsigned*)g_hhi)[i] = 0u;
        ((unsigned*)g_hlo)[i] = 0u;
    }
    if (i == 0) g_bar = 0u;
}

// ---------------------------------------------------------------------------
// Convert inputs and W_ih to bf16 hi/lo split (row-major, same layout).
// ---------------------------------------------------------------------------
__global__ void conv_kernel(const float* __restrict__ inp, const float* __restrict__ Wih) {
    int stride = gridDim.x * blockDim.x;
    int i0 = blockIdx.x * blockDim.x + threadIdx.x;
    // inputs: 16384*256 floats = 1048576 float4
    for (int i = i0; i < 1048576; i += stride) {
        float4 v = ((const float4*)inp)[i];
        __nv_bfloat16 hx = __float2bfloat16(v.x), hy = __float2bfloat16(v.y);
        __nv_bfloat16 hz = __float2bfloat16(v.z), hw = __float2bfloat16(v.w);
        uint2 hi = make_uint2(pack2(hx, hy), pack2(hz, hw));
        uint2 lo = make_uint2(
            pack2(__float2bfloat16(v.x - __bfloat162float(hx)), __float2bfloat16(v.y - __bfloat162float(hy))),
            pack2(__float2bfloat16(v.z - __bfloat162float(hz)), __float2bfloat16(v.w - __bfloat162float(hw))));
        ((uint2*)g_xhi)[i] = hi;
        ((uint2*)g_xlo)[i] = lo;
    }
    // W_ih: 4096*256 floats = 262144 float4
    for (int i = i0; i < 262144; i += stride) {
        float4 v = ((const float4*)Wih)[i];
        __nv_bfloat16 hx = __float2bfloat16(v.x), hy = __float2bfloat16(v.y);
        __nv_bfloat16 hz = __float2bfloat16(v.z), hw = __float2bfloat16(v.w);
        uint2 hi = make_uint2(pack2(hx, hy), pack2(hz, hw));
        uint2 lo = make_uint2(
            pack2(__float2bfloat16(v.x - __bfloat162float(hx)), __float2bfloat16(v.y - __bfloat162float(hy))),
            pack2(__float2bfloat16(v.z - __bfloat162float(hz)), __float2bfloat16(v.w - __bfloat162float(hw))));
        ((uint2*)g_wihhi)[i] = hi;
        ((uint2*)g_wihlo)[i] = lo;
    }
}

// ---------------------------------------------------------------------------
// x_proj via split-bf16 mma.sync.  M=16384 rows (r = b*256+t), N=4096, K=256.
// grid (64 n-tiles, 16); each CTA: W tile (64 cols x 256 k) resident
// fragment-direct in SMEM; loops over 8 M-tiles of 128 rows.
// Warp w owns m rows [w*16, w*16+16), all 64 n cols (8 n8-tiles).
// ---------------------------------------------------------------------------
__global__ __launch_bounds__(256, 1) void xproj_mma_kernel(
    const float* __restrict__ bih, const float* __restrict__ bhh) {
    extern __shared__ char sm[];
    const int tid = threadIdx.x;
    const int lane = tid & 31;
    const int w = tid >> 5;
    const int n0 = blockIdx.x * 64;
    const uint32_t smb = smem_u32(sm);

    // ---- W fragment fill (8192 u32 per half) ----
    // u32 idx = (ks*32 + ln)*16 + q;  q = nt*2 + rr; nl = nt*8 + (ln>>2); kk = rr*8 + (ln&3)*2
    for (int idx = tid; idx < 8192; idx += 256) {
        int q = idx & 15, ln = (idx >> 4) & 31, ks = idx >> 9;
        int nt = q >> 1, rr = q & 1;
        int nl = nt * 8 + (ln >> 2);
        int k = ks * 16 + rr * 8 + (ln & 3) * 2;
        uint32_t vh = *(const uint32_t*)(g_wihhi + (n0 + nl) * II + k);
        uint32_t vl = *(const uint32_t*)(g_wihlo + (n0 + nl) * II + k);
        ((uint32_t*)(sm + XW_HI))[idx] = vh;
        ((uint32_t*)(sm + XW_LO))[idx] = vl;
    }
    __syncthreads();

    // bias per lane (cols this lane's fragments cover)
    const int grp = lane >> 2, tg = lane & 3;
    float bias0[8], bias1[8];
#pragma unroll
    for (int nt = 0; nt < 8; nt++) {
        int g = n0 + nt * 8 + tg * 2;
        bias0[nt] = bih[g] + bhh[g];
        bias1[nt] = bih[g + 1] + bhh[g + 1];
    }

    // A ldmatrix per-lane constants
    const int arow = w * 16 + (lane & 15);
    const int acol = (lane >> 4) * 16;   // byte offset of k-half

    for (int miter = 0; miter < 8; miter++) {
        const int m0 = (blockIdx.y * 8 + miter) * 128;

        float acc[8][4];
#pragma unroll
        for (int z = 0; z < 8; z++)
#pragma unroll
            for (int r = 0; r < 4; r++) acc[z][r] = 0.f;

        // prologue: chunk 0 -> buf 0  (4 x 16B segments per half per thread)
#pragma unroll
        for (int i = 0; i < 4; i++) {
            int s = i * 256 + tid;
            int row = s >> 3, sb = s & 7;
            int gidx = (m0 + row) * 32 + sb;          // uint4 index, ch=0
            uint4 vh = ((const uint4*)g_xhi)[gidx];
            uint4 vl = ((const uint4*)g_xlo)[gidx];
            int off = row * 128 + sb * 16;
            int sw = off ^ ((off >> 3) & 0x70);
            *(uint4*)(sm + XA_HI + sw) = vh;
            *(uint4*)(sm + XA_LO + sw) = vl;
        }
        __syncthreads();

        for (int ch = 0; ch < 4; ch++) {
            const int buf = ch & 1;
            uint4 ph[4], pl[4];
            if (ch < 3) {
#pragma unroll
                for (int i = 0; i < 4; i++) {
                    int s = i * 256 + tid;
                    int row = s >> 3, sb = s & 7;
                    int gidx = (m0 + row) * 32 + (ch + 1) * 8 + sb;
                    ph[i] = ((const uint4*)g_xhi)[gidx];
                    pl[i] = ((const uint4*)g_xlo)[gidx];
                }
            }
            const uint32_t abh = smb + XA_HI + buf * 16384;
            const uint32_t abl = smb + XA_LO + buf * 16384;
#pragma unroll
            for (int kl = 0; kl < 4; kl++) {
                const int ks = ch * 4 + kl;
                int off = arow * 128 + kl * 32 + acol;
                int sw = off ^ ((off >> 3) & 0x70);
                uint32_t ah[4], al[4];
                ldm_x4(ah, abh + sw);
                ldm_x4(al, abl + sw);
                const uint4* wh4 = (const uint4*)(sm + XW_HI) + (ks * 32 + lane) * 4;
                const uint4* wl4 = (const uint4*)(sm + XW_LO) + (ks * 32 + lane) * 4;
#pragma unroll
                for (int q4 = 0; q4 < 4; q4++) {
                    uint4 bh = wh4[q4];
                    uint4 bl = wl4[q4];
                    mma_bf16(acc[2 * q4], ah, bh.x, bh.y);
                    mma_bf16(acc[2 * q4 + 1], ah, bh.z, bh.w);
                    mma_bf16(acc[2 * q4], al, bh.x, bh.y);
                    mma_bf16(acc[2 * q4 + 1], al, bh.z, bh.w);
                    mma_bf16(acc[2 * q4], ah, bl.x, bl.y);
                    mma_bf16(acc[2 * q4 + 1], ah, bl.z, bl.w);
                }
            }
            if (ch < 3) {
                char* dh = sm + XA_HI + (buf ^ 1) * 16384;
                char* dl = sm + XA_LO + (buf ^ 1) * 16384;
#pragma unroll
                for (int i = 0; i < 4; i++) {
                    int s = i * 256 + tid;
                    int row = s >> 3, sb = s & 7;
                    int off = row * 128 + sb * 16;
                    int sw = off ^ ((off >> 3) & 0x70);
                    *(uint4*)(dh + sw) = ph[i];
                    *(uint4*)(dl + sw) = pl[i];
                }
            }
            __syncthreads();
        }

        // epilogue: direct stores (r = b*256 + t -> out row t*64+b)
        int r0 = m0 + w * 16 + grp;
        int r1 = r0 + 8;
        size_t ob0 = ((size_t)(r0 & 255) * BB + (r0 >> 8)) * GG;
        size_t ob1 = ((size_t)(r1 & 255) * BB + (r1 >> 8)) * GG;
#pragma unroll
        for (int nt = 0; nt < 8; nt++) {
            int g = n0 + nt * 8 + tg * 2;
            float2 v0 = make_float2(acc[nt][0] + bias0[nt], acc[nt][1] + bias1[nt]);
            float2 v1 = make_float2(acc[nt][2] + bias0[nt], acc[nt][3] + bias1[nt]);
            *(float2*)&g_xproj[ob0 + g] = v0;
            *(float2*)&g_xproj[ob1 + g] = v1;
        }
    }
}

// ---------------------------------------------------------------------------
// Persistent LSTM recurrence: 128 CTAs x 256 thr. mma.sync bf16 3-term split.
// (mainloop proven in round 3; epilogue now distributed over all 256 threads)
// ---------------------------------------------------------------------------
__global__ __launch_bounds__(256, 1) void lstm_kernel(const float* __restrict__ Whh) {
    extern __shared__ char sm[];
    const int tid = threadIdx.x;
    const int lane = tid & 31;
    const int w = tid >> 5;
    const int mt = w & 3, nh = w >> 2;
    const int hc0 = blockIdx.x * 8;
    const uint32_t smb = smem_u32(sm);

    // ---- one-time: W fragment fill (hi/lo split, fragment-direct layout) ----
    for (int idx = tid; idx < 16384; idx += 256) {
        int r = idx & 3, ln = (idx >> 2) & 31, ks = (idx >> 7) & 63, nhh = idx >> 13;
        int nt = r >> 1;
        int kk = (r & 1) * 8 + (ln & 3) * 2;
        int nl = nhh * 16 + nt * 8 + (ln >> 2);
        int k = ks * 16 + kk;
        int gr = (nl >> 3) * 1024 + hc0 + (nl & 7);
        float w0 = Whh[gr * 1024 + k];
        float w1 = Whh[gr * 1024 + k + 1];
        __nv_bfloat16 h0 = __float2bfloat16(w0), h1 = __float2bfloat16(w1);
        __nv_bfloat16 l0 = __float2bfloat16(w0 - __bfloat162float(h0));
        __nv_bfloat16 l1 = __float2bfloat16(w1 - __bfloat162float(h1));
        ((uint32_t*)(sm + WF_HI))[idx] = pack2(h0, h1);
        ((uint32_t*)(sm + WF_LO))[idx] = pack2(l0, l1);
    }
    __syncthreads();

    // per-thread A-chunk staging constants (2 x 16B segments per thread)
    const int row0 = tid >> 3, s0 = tid & 7;
    const int row1 = (tid + 256) >> 3, s1 = tid & 7;
    int o0 = row0 * 128 + s0 * 16; o0 ^= (o0 >> 3) & 0x70;
    int o1 = row1 * 128 + s1 * 16; o1 ^= (o1 >> 3) & 0x70;

    // A ldmatrix per-lane constants
    const int arow = mt * 16 + (lane & 15);
    const int acol = (lane >> 4) * 16;

    // epilogue ownership: this thread handles states (b, j0) and (b, j0+4)
    const int eb = tid & 63, ej = tid >> 6;   // ej in 0..3
    float c0 = 0.f, c1 = 0.f;

    for (int t = 0; t < TT; t++) {
        const uint4* ghi = (const uint4*)g_hhi[t & 1];
        const uint4* glo = (const uint4*)g_hlo[t & 1];
        const float* xg = g_xproj + (size_t)t * BB * GG;

        // prefetch this thread's xproj values (4 gates x 2 states)
        float xp[8];
#pragma unroll
        for (int q = 0; q < 4; q++) {
            xp[q] = xg[(size_t)eb * GG + q * HH + hc0 + ej];
            xp[4 + q] = xg[(size_t)eb * GG + q * HH + hc0 + ej + 4];
        }

        float acc[2][4];
#pragma unroll
        for (int z = 0; z < 2; z++)
#pragma unroll
            for (int r = 0; r < 4; r++) acc[z][r] = 0.f;

        // prologue: chunk 0 -> buf 0
        {
            uint4 vh0 = __ldcg(ghi + row0 * 128 + s0);
            uint4 vh1 = __ldcg(ghi + row1 * 128 + s1);
            uint4 vl0 = __ldcg(glo + row0 * 128 + s0);
            uint4 vl1 = __ldcg(glo + row1 * 128 + s1);
            *(uint4*)(sm + A_HI + o0) = vh0; *(uint4*)(sm + A_HI + o1) = vh1;
            *(uint4*)(sm + A_LO + o0) = vl0; *(uint4*)(sm + A_LO + o1) = vl1;
        }
        __syncthreads();

        for (int ch = 0; ch < 16; ch++) {
            const int buf = ch & 1;
            uint4 vh0, vh1, vl0, vl1;
            if (ch < 15) {
                int g0 = row0 * 128 + (ch + 1) * 8 + s0;
                int g1 = row1 * 128 + (ch + 1) * 8 + s1;
                vh0 = __ldcg(ghi + g0); vh1 = __ldcg(ghi + g1);
                vl0 = __ldcg(glo + g0); vl1 = __ldcg(glo + g1);
            }
            const uint32_t abh = smb + A_HI + buf * 8192;
            const uint32_t abl = smb + A_LO + buf * 8192;
            const uint32_t* wfh = (const uint32_t*)(sm + WF_HI) + (nh * 64 + ch * 4) * 128 + lane * 4;
            const uint32_t* wfl = (const uint32_t*)(sm + WF_LO) + (nh * 64 + ch * 4) * 128 + lane * 4;
#pragma unroll
            for (int kl = 0; kl < 4; kl++) {
                int off = arow * 128 + kl * 32 + acol;
                int sw = off ^ ((off >> 3) & 0x70);
                uint32_t ah[4], al[4];
                ldm_x4(ah, abh + sw);
                ldm_x4(al, abl + sw);
                uint4 bh = *(const uint4*)(wfh + kl * 128);
                uint4 bl = *(const uint4*)(wfl + kl * 128);
                mma_bf16(acc[0], ah, bh.x, bh.y);
                mma_bf16(acc[1], ah, bh.z, bh.w);
                mma_bf16(acc[0], al, bh.x, bh.y);
                mma_bf16(acc[1], al, bh.z, bh.w);
                mma_bf16(acc[0], ah, bl.x, bl.y);
                mma_bf16(acc[1], ah, bl.z, bl.w);
            }
            if (ch < 15) {
                char* dh = sm + A_HI + (buf ^ 1) * 8192;
                char* dl = sm + A_LO + (buf ^ 1) * 8192;
                *(uint4*)(dh + o0) = vh0; *(uint4*)(dh + o1) = vh1;
                *(uint4*)(dl + o0) = vl0; *(uint4*)(dl + o1) = vl1;
            }
            __syncthreads();
        }

        // epilogue: exchange D fragments via SMEM [32 cols][stride 72]
        float* sg = (float*)sm;
        {
            int grp = lane >> 2, tg = lane & 3;
#pragma unroll
            for (int nt = 0; nt < 2; nt++) {
                int col = nh * 16 + nt * 8 + tg * 2;
                int row = mt * 16 + grp;
                sg[col * 72 + row] = acc[nt][0];
                sg[(col + 1) * 72 + row] = acc[nt][1];
                sg[col * 72 + row + 8] = acc[nt][2];
                sg[(col + 1) * 72 + row + 8] = acc[nt][3];
            }
        }
        __syncthreads();

        // pointwise update distributed: 512 states over 256 threads (2 each)
        {
            __nv_bfloat16* hh = g_hhi[(t + 1) & 1];
            __nv_bfloat16* hl = g_hlo[(t + 1) & 1];
            // state (eb, ej)
            {
                float iv = sg[(0 + ej) * 72 + eb] + xp[0];
                float fv = sg[(8 + ej) * 72 + eb] + xp[1];
                float gv = sg[(16 + ej) * 72 + eb] + xp[2];
                float ov = sg[(24 + ej) * 72 + eb] + xp[3];
                float si = 1.f / (1.f + expf(-iv));
                float sf = 1.f / (1.f + expf(-fv));
                float tg2 = tanhf(gv);
                float so = 1.f / (1.f + expf(-ov));
                float cn = sf * c0 + si * tg2;
                c0 = cn;
                float hn = so * tanhf(cn);
                __nv_bfloat16 hbb = __float2bfloat16(hn);
                hh[eb * HH + hc0 + ej] = hbb;
                hl[eb * HH + hc0 + ej] = __float2bfloat16(hn - __bfloat162float(hbb));
            }
            // state (eb, ej+4)
            {
                int j = ej + 4;
                float iv = sg[(0 + j) * 72 + eb] + xp[4];
                float fv = sg[(8 + j) * 72 + eb] + xp[5];
                float gv = sg[(16 + j) * 72 + eb] + xp[6];
                float ov = sg[(24 + j) * 72 + eb] + xp[7];
                float si = 1.f / (1.f + expf(-iv));
                float sf = 1.f / (1.f + expf(-fv));
                float tg2 = tanhf(gv);
                float so = 1.f / (1.f + expf(-ov));
                float cn = sf * c1 + si * tg2;
                c1 = cn;
                float hn = so * tanhf(cn);
                __nv_bfloat16 hbb = __float2bfloat16(hn);
                hh[eb * HH + hc0 + j] = hbb;
                hl[eb * HH + hc0 + j] = __float2bfloat16(hn - __bfloat162float(hbb));
            }
        }
        __threadfence();
        __syncthreads();
        if (tid == 0) {
            atomicAdd(&g_bar, 1u);
            unsigned target = (unsigned)NCTA * (t + 1), v;
            do {
                asm volatile("ld.acquire.gpu.global.u32 %0, [%1];" : "=r"(v) : "l"(&g_bar));
            } while (v < target);
        }
        __syncthreads();
    }
}

// ---------------------------------------------------------------------------
// logits = h_last @ fc_w^T + fc_b; out = log_softmax.  grid=64, block=256.
// ---------------------------------------------------------------------------
__global__ __launch_bounds__(256) void fc_kernel(const float* __restrict__ fcw,
                                                 const float* __restrict__ fcb,
                                                 float* __restrict__ out) {
    __shared__ float sh[HH];
    __shared__ float sl[64];
    __shared__ float s_red[2];
    int b = blockIdx.x;
    int tid = threadIdx.x;
    int w = tid >> 5, lane = tid & 31;

    // stage h = hi + lo into SMEM (T=256 even -> final h in buffer 0)
    {
        uint2 vh = ((const uint2*)(g_hhi[0] + b * HH))[tid];
        uint2 vl = ((const uint2*)(g_hlo[0] + b * HH))[tid];
        float2 h0 = unpack2(vh.x), h1 = unpack2(vh.y);
        float2 l0 = unpack2(vl.x), l1 = unpack2(vl.y);
        float4 f = make_float4(h0.x + l0.x, h0.y + l0.y, h1.x + l1.x, h1.y + l1.y);
        ((float4*)sh)[tid] = f;
    }
    __syncthreads();

    // each warp: 8 classes, lane-parallel over K
#pragma unroll
    for (int cc = 0; cc < 8; cc++) {
        int c = w * 8 + cc;
        float s = 0.f;
        if (c < CC) {
            const float* wr = fcw + c * HH;
#pragma unroll 8
            for (int i = 0; i < 32; i++) {
                int k = i * 32 + lane;
                s += sh[k] * wr[k];
            }
        }
#pragma unroll
        for (int off = 16; off > 0; off >>= 1) s += __shfl_xor_sync(0xFFFFFFFF, s, off);
        if (lane == 0) sl[c] = (c < CC) ? s + fcb[c] : -1e30f;
    }
    __syncthreads();

    if (w == 0) {
        float v0 = sl[lane], v1 = sl[lane + 32];
        float m = fmaxf(v0, v1);
#pragma unroll
        for (int off = 16; off > 0; off >>= 1) m = fmaxf(m, __shfl_xor_sync(0xFFFFFFFF, m, off));
        float e = expf(v0 - m) + expf(v1 - m);
#pragma unroll
        for (int off = 16; off > 0; off >>= 1) e += __shfl_xor_sync(0xFFFFFFFF, e, off);
        if (lane == 0) { s_red[0] = m; s_red[1] = logf(e); }
    }
    __syncthreads();
    if (tid < CC) out[b * CC + tid] = sl[tid] - s_red[0] - s_red[1];
}

// ---------------------------------------------------------------------------
extern "C" void kernel_launch(void* const* d_in, const int* in_sizes, int n_in,
                              void* d_out, int out_size) {
    const float* inp = (const float*)d_in[0];   // [B,T,I]
    const float* Wih = (const float*)d_in[1];   // [4H,I]
    const float* Whh = (const float*)d_in[2];   // [4H,H]
    const float* bih = (const float*)d_in[3];   // [4H]
    const float* bhh = (const float*)d_in[4];   // [4H]
    const float* fcw = (const float*)d_in[5];   // [C,H]
    const float* fcb = (const float*)d_in[6];   // [C]
    float* out = (float*)d_out;                 // [B,C]

    cudaFuncSetAttribute(lstm_kernel, cudaFuncAttributeMaxDynamicSharedMemorySize, SMEM_DYN);
    cudaFuncSetAttribute(xproj_mma_kernel, cudaFuncAttributeMaxDynamicSharedMemorySize, SMEM_X);

    zero_kernel<<<512, 256>>>();
    conv_kernel<<<1024, 256>>>(inp, Wih);

    dim3 gx(64, 16);
    xproj_mma_kernel<<<gx, 256, SMEM_X>>>(bih, bhh);

    lstm_kernel<<<NCTA, 256, SMEM_DYN>>>(Whh);

    fc_kernel<<<BB, 64 * 4>>>(fcw, fcb, out);
}

// round 5
// speedup vs baseline: 2.5438x; 1.0057x over previous
#include <cuda_runtime.h>
#include <cuda_bf16.h>
#include <math.h>
#include <cstdint>

// Problem dims
constexpr int BB = 64;    // batch
constexpr int TT = 256;   // time steps
constexpr int II = 256;   // input dim
constexpr int HH = 1024;  // hidden
constexpr int CC = 60;    // classes
constexpr int GG = 4096;  // 4*H
constexpr int NCTA = 128; // persistent CTAs; each owns 8 h-cols x 4 gates = 32 gate cols

// Dynamic SMEM layout (lstm_kernel): k128 chunks
constexpr int A_HI = 0;        // 2 bufs x 16KB (64 rows x 128 bf16, row=256B, seg-swizzled)
constexpr int A_LO = 32768;    // 2 bufs x 16KB
constexpr int WF_HI = 65536;   // 64KB fragment-direct W hi
constexpr int WF_LO = 131072;  // 64KB fragment-direct W lo
constexpr int SMEM_DYN = 196608;

// Dynamic SMEM layout (xproj_mma kernel)
constexpr int XA_HI = 0;       // 2 bufs x 16KB (128 rows x 64 bf16, SW128)
constexpr int XA_LO = 32768;   // 2 bufs x 16KB
constexpr int XW_HI = 65536;   // 32KB fragment-direct W_ih hi (64 cols x 256 k)
constexpr int XW_LO = 98304;   // 32KB
constexpr int SMEM_X = 131072;

// Scratch (__device__ globals: allocation-free)
__device__ float g_xproj[(size_t)TT * BB * GG];   // [t][b][g]
__device__ __nv_bfloat16 g_hhi[2][BB * HH];       // h hi, ping-pong
__device__ __nv_bfloat16 g_hlo[2][BB * HH];       // h lo, ping-pong
__device__ __nv_bfloat16 g_xhi[BB * TT * II];     // inputs hi  [(b*T+t)][i]
__device__ __nv_bfloat16 g_xlo[BB * TT * II];
__device__ __nv_bfloat16 g_wihhi[GG * II];        // W_ih hi [g][i]
__device__ __nv_bfloat16 g_wihlo[GG * II];
__device__ unsigned g_cnt[8];                     // per-column-group step counters

// ---------------------------------------------------------------------------
// helpers
// ---------------------------------------------------------------------------
__device__ __forceinline__ uint32_t smem_u32(const void* p) {
    uint32_t a;
    asm("{ .reg .u64 t; cvta.to.shared.u64 t, %1; cvt.u32.u64 %0, t; }" : "=r"(a) : "l"(p));
    return a;
}
__device__ __forceinline__ void ldm_x4(uint32_t* r, uint32_t addr) {
    asm volatile("ldmatrix.sync.aligned.m8n8.x4.shared.b16 {%0,%1,%2,%3}, [%4];"
                 : "=r"(r[0]), "=r"(r[1]), "=r"(r[2]), "=r"(r[3]) : "r"(addr));
}
__device__ __forceinline__ void mma_bf16(float* d, const uint32_t* a, uint32_t b0, uint32_t b1) {
    asm volatile(
        "mma.sync.aligned.m16n8k16.row.col.f32.bf16.bf16.f32 "
        "{%0,%1,%2,%3}, {%4,%5,%6,%7}, {%8,%9}, {%0,%1,%2,%3};"
        : "+f"(d[0]), "+f"(d[1]), "+f"(d[2]), "+f"(d[3])
        : "r"(a[0]), "r"(a[1]), "r"(a[2]), "r"(a[3]), "r"(b0), "r"(b1));
}
__device__ __forceinline__ uint32_t pack2(__nv_bfloat16 a, __nv_bfloat16 b) {
    return (uint32_t)*(uint16_t*)&a | ((uint32_t)*(uint16_t*)&b << 16);
}
__device__ __forceinline__ float2 unpack2(uint32_t v) {
    __nv_bfloat16 a, b;
    uint16_t x = (uint16_t)v, y = (uint16_t)(v >> 16);
    a = *(__nv_bfloat16*)&x; b = *(__nv_bfloat16*)&y;
    return make_float2(__bfloat162float(a), __bfloat162float(b));
}
__device__ __forceinline__ void poll_ge(const unsigned* p, unsigned tgt) {
    unsigned v;
    do {
        asm volatile("ld.acquire.gpu.global.u32 %0, [%1];" : "=r"(v) : "l"(p) : "memory");
    } while (v < tgt);
}
__device__ __forceinline__ float fsigmoid(float x) {
    return __fdividef(1.f, 1.f + __expf(-x));
}
__device__ __forceinline__ float ftanh(float x) {
    return 1.f - __fdividef(2.f, __expf(2.f * x) + 1.f);
}

// ---------------------------------------------------------------------------
// Zero-init h buffers + group counters.
// ---------------------------------------------------------------------------
__global__ void zero_kernel() {
    int i = blockIdx.x * blockDim.x + threadIdx.x;
    if (i < BB * HH) {
        ((unsigned*)g_hhi)[i] = 0u;
        ((unsigned*)g_hlo)[i] = 0u;
    }
    if (i < 8) g_cnt[i] = 0u;
}

// ---------------------------------------------------------------------------
// Convert inputs and W_ih to bf16 hi/lo split (row-major, same layout).
// ---------------------------------------------------------------------------
__global__ void conv_kernel(const float* __restrict__ inp, const float* __restrict__ Wih) {
    int stride = gridDim.x * blockDim.x;
    int i0 = blockIdx.x * blockDim.x + threadIdx.x;
    for (int i = i0; i < 1048576; i += stride) {
        float4 v = ((const float4*)inp)[i];
        __nv_bfloat16 hx = __float2bfloat16(v.x), hy = __float2bfloat16(v.y);
        __nv_bfloat16 hz = __float2bfloat16(v.z), hw = __float2bfloat16(v.w);
        uint2 hi = make_uint2(pack2(hx, hy), pack2(hz, hw));
        uint2 lo = make_uint2(
            pack2(__float2bfloat16(v.x - __bfloat162float(hx)), __float2bfloat16(v.y - __bfloat162float(hy))),
            pack2(__float2bfloat16(v.z - __bfloat162float(hz)), __float2bfloat16(v.w - __bfloat162float(hw))));
        ((uint2*)g_xhi)[i] = hi;
        ((uint2*)g_xlo)[i] = lo;
    }
    for (int i = i0; i < 262144; i += stride) {
        float4 v = ((const float4*)Wih)[i];
        __nv_bfloat16 hx = __float2bfloat16(v.x), hy = __float2bfloat16(v.y);
        __nv_bfloat16 hz = __float2bfloat16(v.z), hw = __float2bfloat16(v.w);
        uint2 hi = make_uint2(pack2(hx, hy), pack2(hz, hw));
        uint2 lo = make_uint2(
            pack2(__float2bfloat16(v.x - __bfloat162float(hx)), __float2bfloat16(v.y - __bfloat162float(hy))),
            pack2(__float2bfloat16(v.z - __bfloat162float(hz)), __float2bfloat16(v.w - __bfloat162float(hw))));
        ((uint2*)g_wihhi)[i] = hi;
        ((uint2*)g_wihlo)[i] = lo;
    }
}

// ---------------------------------------------------------------------------
// x_proj via split-bf16 mma.sync (proven round 4).
// ---------------------------------------------------------------------------
__global__ __launch_bounds__(256, 1) void xproj_mma_kernel(
    const float* __restrict__ bih, const float* __restrict__ bhh) {
    extern __shared__ char sm[];
    const int tid = threadIdx.x;
    const int lane = tid & 31;
    const int w = tid >> 5;
    const int n0 = blockIdx.x * 64;
    const uint32_t smb = smem_u32(sm);

    for (int idx = tid; idx < 8192; idx += 256) {
        int q = idx & 15, ln = (idx >> 4) & 31, ks = idx >> 9;
        int nt = q >> 1, rr = q & 1;
        int nl = nt * 8 + (ln >> 2);
        int k = ks * 16 + rr * 8 + (ln & 3) * 2;
        uint32_t vh = *(const uint32_t*)(g_wihhi + (n0 + nl) * II + k);
        uint32_t vl = *(const uint32_t*)(g_wihlo + (n0 + nl) * II + k);
        ((uint32_t*)(sm + XW_HI))[idx] = vh;
        ((uint32_t*)(sm + XW_LO))[idx] = vl;
    }
    __syncthreads();

    const int grp = lane >> 2, tg = lane & 3;
    float bias0[8], bias1[8];
#pragma unroll
    for (int nt = 0; nt < 8; nt++) {
        int g = n0 + nt * 8 + tg * 2;
        bias0[nt] = bih[g] + bhh[g];
        bias1[nt] = bih[g + 1] + bhh[g + 1];
    }

    const int arow = w * 16 + (lane & 15);
    const int acol = (lane >> 4) * 16;

    for (int miter = 0; miter < 8; miter++) {
        const int m0 = (blockIdx.y * 8 + miter) * 128;

        float acc[8][4];
#pragma unroll
        for (int z = 0; z < 8; z++)
#pragma unroll
            for (int r = 0; r < 4; r++) acc[z][r] = 0.f;

#pragma unroll
        for (int i = 0; i < 4; i++) {
            int s = i * 256 + tid;
            int row = s >> 3, sb = s & 7;
            int gidx = (m0 + row) * 32 + sb;
            uint4 vh = ((const uint4*)g_xhi)[gidx];
            uint4 vl = ((const uint4*)g_xlo)[gidx];
            int off = row * 128 + sb * 16;
            int sw = off ^ ((off >> 3) & 0x70);
            *(uint4*)(sm + XA_HI + sw) = vh;
            *(uint4*)(sm + XA_LO + sw) = vl;
        }
        __syncthreads();

        for (int ch = 0; ch < 4; ch++) {
            const int buf = ch & 1;
            uint4 ph[4], pl[4];
            if (ch < 3) {
#pragma unroll
                for (int i = 0; i < 4; i++) {
                    int s = i * 256 + tid;
                    int row = s >> 3, sb = s & 7;
                    int gidx = (m0 + row) * 32 + (ch + 1) * 8 + sb;
                    ph[i] = ((const uint4*)g_xhi)[gidx];
                    pl[i] = ((const uint4*)g_xlo)[gidx];
                }
            }
            const uint32_t abh = smb + XA_HI + buf * 16384;
            const uint32_t abl = smb + XA_LO + buf * 16384;
#pragma unroll
            for (int kl = 0; kl < 4; kl++) {
                const int ks = ch * 4 + kl;
                int off = arow * 128 + kl * 32 + acol;
                int sw = off ^ ((off >> 3) & 0x70);
                uint32_t ah[4], al[4];
                ldm_x4(ah, abh + sw);
                ldm_x4(al, abl + sw);
                const uint4* wh4 = (const uint4*)(sm + XW_HI) + (ks * 32 + lane) * 4;
                const uint4* wl4 = (const uint4*)(sm + XW_LO) + (ks * 32 + lane) * 4;
#pragma unroll
                for (int q4 = 0; q4 < 4; q4++) {
                    uint4 bh = wh4[q4];
                    uint4 bl = wl4[q4];
                    mma_bf16(acc[2 * q4], ah, bh.x, bh.y);
                    mma_bf16(acc[2 * q4 + 1], ah, bh.z, bh.w);
                    mma_bf16(acc[2 * q4], al, bh.x, bh.y);
                    mma_bf16(acc[2 * q4 + 1], al, bh.z, bh.w);
                    mma_bf16(acc[2 * q4], ah, bl.x, bl.y);
                    mma_bf16(acc[2 * q4 + 1], ah, bl.z, bl.w);
                }
            }
            if (ch < 3) {
                char* dh = sm + XA_HI + (buf ^ 1) * 16384;
                char* dl = sm + XA_LO + (buf ^ 1) * 16384;
#pragma unroll
                for (int i = 0; i < 4; i++) {
                    int s = i * 256 + tid;
                    int row = s >> 3, sb = s & 7;
                    int off = row * 128 + sb * 16;
                    int sw = off ^ ((off >> 3) & 0x70);
                    *(uint4*)(dh + sw) = ph[i];
                    *(uint4*)(dl + sw) = pl[i];
                }
            }
            __syncthreads();
        }

        int r0 = m0 + w * 16 + grp;
        int r1 = r0 + 8;
        size_t ob0 = ((size_t)(r0 & 255) * BB + (r0 >> 8)) * GG;
        size_t ob1 = ((size_t)(r1 & 255) * BB + (r1 >> 8)) * GG;
#pragma unroll
        for (int nt = 0; nt < 8; nt++) {
            int g = n0 + nt * 8 + tg * 2;
            float2 v0 = make_float2(acc[nt][0] + bias0[nt], acc[nt][1] + bias1[nt]);
            float2 v1 = make_float2(acc[nt][2] + bias0[nt], acc[nt][3] + bias1[nt]);
            *(float2*)&g_xproj[ob0 + g] = v0;
            *(float2*)&g_xproj[ob1 + g] = v1;
        }
    }
}

// ---------------------------------------------------------------------------
// Persistent LSTM recurrence: 128 CTAs x 256 thr, mma.sync bf16 3-term split.
// k=128 chunks (8/step), producer-group counters instead of a grid barrier,
// fast-math epilogue. Group g (=bx>>4) covers h cols [128g, 128g+128).
// ---------------------------------------------------------------------------
__global__ __launch_bounds__(256, 1) void lstm_kernel(const float* __restrict__ Whh) {
    extern __shared__ char sm[];
    const int tid = threadIdx.x;
    const int lane = tid & 31;
    const int w = tid >> 5;
    const int mt = w & 3, nh = w >> 2;
    const int hc0 = blockIdx.x * 8;
    const uint32_t smb = smem_u32(sm);

    // ---- one-time: W fragment fill (hi/lo split, fragment-direct layout) ----
    for (int idx = tid; idx < 16384; idx += 256) {
        int r = idx & 3, ln = (idx >> 2) & 31, ks = (idx >> 7) & 63, nhh = idx >> 13;
        int nt = r >> 1;
        int kk = (r & 1) * 8 + (ln & 3) * 2;
        int nl = nhh * 16 + nt * 8 + (ln >> 2);
        int k = ks * 16 + kk;
        int gr = (nl >> 3) * 1024 + hc0 + (nl & 7);
        float w0 = Whh[gr * 1024 + k];
        float w1 = Whh[gr * 1024 + k + 1];
        __nv_bfloat16 h0 = __float2bfloat16(w0), h1 = __float2bfloat16(w1);
        __nv_bfloat16 l0 = __float2bfloat16(w0 - __bfloat162float(h0));
        __nv_bfloat16 l1 = __float2bfloat16(w1 - __bfloat162float(h1));
        ((uint32_t*)(sm + WF_HI))[idx] = pack2(h0, h1);
        ((uint32_t*)(sm + WF_LO))[idx] = pack2(l0, l1);
    }
    __syncthreads();

    // staging constants: thread handles 4 x 16B segments per half per chunk
    int ssw[4], sgix[4];
#pragma unroll
    for (int i = 0; i < 4; i++) {
        int s = i * 256 + tid;
        int row = s >> 4, seg = s & 15;
        ssw[i] = row * 256 + ((seg ^ (row & 7)) << 4);
        sgix[i] = row * 128 + seg;          // + ch*16 per chunk (uint4 units)
    }

    // A ldmatrix per-lane constants (row = arow, seg swizzled per row)
    const int arow = mt * 16 + (lane & 15);
    const int ahalf = lane >> 4;            // k-half within kstep

    // epilogue ownership: this thread handles states (b, ej) and (b, ej+4)
    const int eb = tid & 63, ej = tid >> 6;
    float c0 = 0.f, c1 = 0.f;

    for (int t = 0; t < TT; t++) {
        const uint4* ghi = (const uint4*)g_hhi[t & 1];
        const uint4* glo = (const uint4*)g_hlo[t & 1];
        const float* xg = g_xproj + (size_t)t * BB * GG;
        const unsigned tgt = 16u * (unsigned)t;

        // prefetch this thread's xproj values (4 gates x 2 states)
        float xp[8];
#pragma unroll
        for (int q = 0; q < 4; q++) {
            xp[q] = xg[(size_t)eb * GG + q * HH + hc0 + ej];
            xp[4 + q] = xg[(size_t)eb * GG + q * HH + hc0 + ej + 4];
        }

        float acc[2][4];
#pragma unroll
        for (int z = 0; z < 2; z++)
#pragma unroll
            for (int r = 0; r < 4; r++) acc[z][r] = 0.f;

        // prologue: wait for group 0 producers, stage chunk 0 -> buf 0
        if (t) {
            if (lane == 0) poll_ge(&g_cnt[0], tgt);
            __syncwarp();
        }
        {
            uint4 vh[4], vl[4];
#pragma unroll
            for (int i = 0; i < 4; i++) { vh[i] = __ldcg(ghi + sgix[i]); vl[i] = __ldcg(glo + sgix[i]); }
#pragma unroll
            for (int i = 0; i < 4; i++) {
                *(uint4*)(sm + A_HI + ssw[i]) = vh[i];
                *(uint4*)(sm + A_LO + ssw[i]) = vl[i];
            }
        }
        __syncthreads();

        for (int ch = 0; ch < 8; ch++) {
            const int buf = ch & 1;
            uint4 ph[4], pl[4];
            if (ch < 7) {
                if (t) {
                    if (lane == 0) poll_ge(&g_cnt[ch + 1], tgt);
                    __syncwarp();
                }
#pragma unroll
                for (int i = 0; i < 4; i++) {
                    ph[i] = __ldcg(ghi + sgix[i] + (ch + 1) * 16);
                    pl[i] = __ldcg(glo + sgix[i] + (ch + 1) * 16);
                }
            }
            const uint32_t abh = smb + A_HI + buf * 16384;
            const uint32_t abl = smb + A_LO + buf * 16384;
            const uint4* wfh = (const uint4*)(sm + WF_HI) + (nh * 64 + ch * 8) * 32 + lane;
            const uint4* wfl = (const uint4*)(sm + WF_LO) + (nh * 64 + ch * 8) * 32 + lane;
#pragma unroll
            for (int kl = 0; kl < 8; kl++) {
                int seg = kl * 2 + ahalf;
                int sw = arow * 256 + ((seg ^ (arow & 7)) << 4);
                uint32_t ah[4], al[4];
                ldm_x4(ah, abh + sw);
                ldm_x4(al, abl + sw);
                uint4 bh = wfh[kl * 32];
                uint4 bl = wfl[kl * 32];
                mma_bf16(acc[0], ah, bh.x, bh.y);
                mma_bf16(acc[1], ah, bh.z, bh.w);
                mma_bf16(acc[0], al, bh.x, bh.y);
                mma_bf16(acc[1], al, bh.z, bh.w);
                mma_bf16(acc[0], ah, bl.x, bl.y);
                mma_bf16(acc[1], ah, bl.z, bl.w);
            }
            if (ch < 7) {
                char* dh = sm + A_HI + (buf ^ 1) * 16384;
                char* dl = sm + A_LO + (buf ^ 1) * 16384;
#pragma unroll
                for (int i = 0; i < 4; i++) {
                    *(uint4*)(dh + ssw[i]) = ph[i];
                    *(uint4*)(dl + ssw[i]) = pl[i];
                }
            }
            __syncthreads();
        }

        // epilogue: exchange D fragments via SMEM [32 cols][stride 72]
        float* sg = (float*)sm;
        {
            int grp = lane >> 2, tg = lane & 3;
#pragma unroll
            for (int nt = 0; nt < 2; nt++) {
                int col = nh * 16 + nt * 8 + tg * 2;
                int row = mt * 16 + grp;
                sg[col * 72 + row] = acc[nt][0];
                sg[(col + 1) * 72 + row] = acc[nt][1];
                sg[col * 72 + row + 8] = acc[nt][2];
                sg[(col + 1) * 72 + row + 8] = acc[nt][3];
            }
        }
        __syncthreads();

        // pointwise update (fast math): 512 states over 256 threads (2 each)
        {
            __nv_bfloat16* hh = g_hhi[(t + 1) & 1];
            __nv_bfloat16* hl = g_hlo[(t + 1) & 1];
            {
                float iv = sg[(0 + ej) * 72 + eb] + xp[0];
                float fv = sg[(8 + ej) * 72 + eb] + xp[1];
                float gv = sg[(16 + ej) * 72 + eb] + xp[2];
                float ov = sg[(24 + ej) * 72 + eb] + xp[3];
                float cn = fsigmoid(fv) * c0 + fsigmoid(iv) * ftanh(gv);
                c0 = cn;
                float hn = fsigmoid(ov) * ftanh(cn);
                __nv_bfloat16 hbb = __float2bfloat16(hn);
                hh[eb * HH + hc0 + ej] = hbb;
                hl[eb * HH + hc0 + ej] = __float2bfloat16(hn - __bfloat162float(hbb));
            }
            {
                int j = ej + 4;
                float iv = sg[(0 + j) * 72 + eb] + xp[4];
                float fv = sg[(8 + j) * 72 + eb] + xp[5];
                float gv = sg[(16 + j) * 72 + eb] + xp[6];
                float ov = sg[(24 + j) * 72 + eb] + xp[7];
                float cn = fsigmoid(fv) * c1 + fsigmoid(iv) * ftanh(gv);
                c1 = cn;
                float hn = fsigmoid(ov) * ftanh(cn);
                __nv_bfloat16 hbb = __float2bfloat16(hn);
                hh[eb * HH + hc0 + j] = hbb;
                hl[eb * HH + hc0 + j] = __float2bfloat16(hn - __bfloat162float(hbb));
            }
        }
        __syncthreads();
        if (tid == 0) {
            __threadfence();                            // order h stores (gpu scope)
            atomicAdd(&g_cnt[blockIdx.x >> 4], 1u);     // signal this group's step done
        }
    }
}

// ---------------------------------------------------------------------------
// logits = h_last @ fc_w^T + fc_b; out = log_softmax.  grid=64, block=256.
// ---------------------------------------------------------------------------
__global__ __launch_bounds__(256) void fc_kernel(const float* __restrict__ fcw,
                                                 const float* __restrict__ fcb,
                                                 float* __restrict__ out) {
    __shared__ float sh[HH];
    __shared__ float sl[64];
    __shared__ float s_red[2];
    int b = blockIdx.x;
    int tid = threadIdx.x;
    int w = tid >> 5, lane = tid & 31;

    {
        uint2 vh = ((const uint2*)(g_hhi[0] + b * HH))[tid];
        uint2 vl = ((const uint2*)(g_hlo[0] + b * HH))[tid];
        float2 h0 = unpack2(vh.x), h1 = unpack2(vh.y);
        float2 l0 = unpack2(vl.x), l1 = unpack2(vl.y);
        float4 f = make_float4(h0.x + l0.x, h0.y + l0.y, h1.x + l1.x, h1.y + l1.y);
        ((float4*)sh)[tid] = f;
    }
    __syncthreads();

#pragma unroll
    for (int cc = 0; cc < 8; cc++) {
        int c = w * 8 + cc;
        float s = 0.f;
        if (c < CC) {
            const float* wr = fcw + c * HH;
#pragma unroll 8
            for (int i = 0; i < 32; i++) {
                int k = i * 32 + lane;
                s += sh[k] * wr[k];
            }
        }
#pragma unroll
        for (int off = 16; off > 0; off >>= 1) s += __shfl_xor_sync(0xFFFFFFFF, s, off);
        if (lane == 0) sl[c] = (c < CC) ? s + fcb[c] : -1e30f;
    }
    __syncthreads();

    if (w == 0) {
        float v0 = sl[lane], v1 = sl[lane + 32];
        float m = fmaxf(v0, v1);
#pragma unroll
        for (int off = 16; off > 0; off >>= 1) m = fmaxf(m, __shfl_xor_sync(0xFFFFFFFF, m, off));
        float e = expf(v0 - m) + expf(v1 - m);
#pragma unroll
        for (int off = 16; off > 0; off >>= 1) e += __shfl_xor_sync(0xFFFFFFFF, e, off);
        if (lane == 0) { s_red[0] = m; s_red[1] = logf(e); }
    }
    __syncthreads();
    if (tid < CC) out[b * CC + tid] = sl[tid] - s_red[0] - s_red[1];
}

// ---------------------------------------------------------------------------
extern "C" void kernel_launch(void* const* d_in, const int* in_sizes, int n_in,
                              void* d_out, int out_size) {
    const float* inp = (const float*)d_in[0];   // [B,T,I]
    const float* Wih = (const float*)d_in[1];   // [4H,I]
    const float* Whh = (const float*)d_in[2];   // [4H,H]
    const float* bih = (const float*)d_in[3];   // [4H]
    const float* bhh = (const float*)d_in[4];   // [4H]
    const float* fcw = (const float*)d_in[5];   // [C,H]
    const float* fcb = (const float*)d_in[6];   // [C]
    float* out = (float*)d_out;                 // [B,C]

    cudaFuncSetAttribute(lstm_kernel, cudaFuncAttributeMaxDynamicSharedMemorySize, SMEM_DYN);
    cudaFuncSetAttribute(xproj_mma_kernel, cudaFuncAttributeMaxDynamicSharedMemorySize, SMEM_X);

    zero_kernel<<<512, 256>>>();
    conv_kernel<<<1024, 256>>>(inp, Wih);

    dim3 gx(64, 16);
    xproj_mma_kernel<<<gx, 256, SMEM_X>>>(bih, bhh);

    lstm_kernel<<<NCTA, 256, SMEM_DYN>>>(Whh);

    fc_kernel<<<BB, 64 * 4>>>(fcw, fcb, out);
}